// round 7
// baseline (speedup 1.0000x reference)
#include <cuda_runtime.h>
#include <cuda_bf16.h>
#include <cstdint>

// out = tanh( Xa @ W1'^T + T[b] ),  T = s @ W2^T,  s[b] = sum_a x[b,a,:]
// W1' = Wh - Wc/7, W2 = Wc/7. Split-bf16 HMMA (xh*Wh + xh*Wl + xl*Wh).
// 128-row tiles, double-buffered x smem, T-GEMM pipelined one tile ahead,
// permuted N-columns for STG.128 epilogue.

#define NTILES 4096
#define TPITCH 68

#define XH0 0
#define XL0 16384
#define XH1 32768
#define XL1 49152
#define W1L 65536
#define W2H 73728
#define W2L 81920
#define SH  90112
#define SL  92160
#define T0  94208
#define T1  98560
#define SMEM_SZ 102912

__device__ __forceinline__ uint32_t smem_u32(const void* p) {
    uint32_t a;
    asm("{ .reg .u64 t; cvta.to.shared.u64 t, %1; cvt.u32.u64 %0, t; }"
        : "=r"(a) : "l"(p));
    return a;
}

__device__ __forceinline__ void mma_bf16(float* c, const uint32_t* a,
                                         uint32_t b0, uint32_t b1) {
    asm volatile(
        "mma.sync.aligned.m16n8k16.row.col.f32.bf16.bf16.f32 "
        "{%0,%1,%2,%3}, {%4,%5,%6,%7}, {%8,%9}, {%0,%1,%2,%3};"
        : "+f"(c[0]), "+f"(c[1]), "+f"(c[2]), "+f"(c[3])
        : "r"(a[0]), "r"(a[1]), "r"(a[2]), "r"(a[3]), "r"(b0), "r"(b1));
}

__device__ __forceinline__ void ldsm4(uint32_t* r, uint32_t addr) {
    asm volatile(
        "ldmatrix.sync.aligned.m8n8.x4.shared.b16 {%0,%1,%2,%3}, [%4];"
        : "=r"(r[0]), "=r"(r[1]), "=r"(r[2]), "=r"(r[3]) : "r"(addr));
}

__device__ __forceinline__ void ldsm2(uint32_t* r, uint32_t addr) {
    asm volatile(
        "ldmatrix.sync.aligned.m8n8.x2.shared.b16 {%0,%1}, [%2];"
        : "=r"(r[0]), "=r"(r[1]) : "r"(addr));
}

__device__ __forceinline__ float tanh_fast(float y) {
    float r;
    asm("tanh.approx.f32 %0, %1;" : "=f"(r) : "f"(y));
    return r;
}

__device__ __forceinline__ void split2(float a, float b, uint32_t& h,
                                       uint32_t& l) {
    __nv_bfloat162 hb = __float22bfloat162_rn(make_float2(a, b));
    float2 g = __bfloat1622float2(hb);
    __nv_bfloat162 lb = __float22bfloat162_rn(make_float2(a - g.x, b - g.y));
    h = *reinterpret_cast<uint32_t*>(&hb);
    l = *reinterpret_cast<uint32_t*>(&lb);
}

// Coalesced fp32 tile load: thread covers rows {tid>>2, 64+tid>>2}, 16 cols.
__device__ __forceinline__ void stage_ldg(const float* xt, int tid,
                                          float4 v[2][4]) {
    const float4* p = (const float4*)(xt + (tid >> 2) * 64 + (tid & 3) * 16);
#pragma unroll
    for (int P = 0; P < 2; P++)
#pragma unroll
        for (int i = 0; i < 4; i++) v[P][i] = p[P * 1024 + i];
}

// Split-bf16 convert + swizzled STS.128 into buffers xh/xl.
__device__ __forceinline__ void stage_sts(char* sm, uint32_t xh, uint32_t xl,
                                          int tid, float4 v[2][4]) {
    const int r0 = tid >> 2, qc = tid & 3;
#pragma unroll
    for (int P = 0; P < 2; P++) {
        int r = r0 + (P << 6);
        uint32_t rowoff = (uint32_t)(r << 7);
        int r7 = r & 7;
#pragma unroll
        for (int u = 0; u < 2; u++) {
            float4 a = v[P][2 * u], b = v[P][2 * u + 1];
            uint32_t h0, l0, h1, l1, h2, l2, h3, l3;
            split2(a.x, a.y, h0, l0);
            split2(a.z, a.w, h1, l1);
            split2(b.x, b.y, h2, l2);
            split2(b.z, b.w, h3, l3);
            uint32_t off = rowoff + (((((qc << 1) + u) ^ r7)) << 4);
            *(uint4*)(sm + xh + off) = make_uint4(h0, h1, h2, h3);
            *(uint4*)(sm + xl + off) = make_uint4(l0, l1, l2, l3);
        }
    }
}

__global__ void __launch_bounds__(256, 2)
comm_v6(const float* __restrict__ x, const float* __restrict__ Wh,
        const float* __restrict__ Wc, float* __restrict__ out) {
    extern __shared__ char sm[];
    const uint32_t sb = smem_u32(sm);

    const int tid = threadIdx.x;
    const int w = tid >> 5;
    const int lane = tid & 31;
    const int g = w >> 1, c = w & 1;
    const int q = lane >> 2, j = lane & 3;

    // ---- weight smem tiles: W1-lo, W2-hi, W2-lo (logical rows, swizzled) ----
    for (int i = tid; i < 4096; i += 256) {
        int n = i >> 6, k = i & 63;
        float cc = Wc[i] * (1.0f / 7.0f);
        float w1 = Wh[i] - cc;
        uint32_t off =
            (uint32_t)(n << 7) + ((((k >> 3) ^ (n & 7))) << 4) + ((k & 7) << 1);
        __nv_bfloat16 w1h = __float2bfloat16(w1);
        *(__nv_bfloat16*)(sm + W1L + off) =
            __float2bfloat16(w1 - __bfloat162float(w1h));
        __nv_bfloat16 cch = __float2bfloat16(cc);
        *(__nv_bfloat16*)(sm + W2H + off) = cch;
        *(__nv_bfloat16*)(sm + W2L + off) =
            __float2bfloat16(cc - __bfloat162float(cch));
    }

    // ---- W1'-hi B fragments in registers, with permuted logical columns ----
    // frag n-position p -> logical col (c<<5)+((nb>>1)<<4)+((p>>1)<<2)+((nb&1)<<1)+(p&1)
    uint32_t bWh[4][4][2];
#pragma unroll
    for (int ks = 0; ks < 4; ks++) {
#pragma unroll
        for (int nb = 0; nb < 4; nb++) {
            int n = (c << 5) + ((nb >> 1) << 4) + ((q >> 1) << 2) +
                    ((nb & 1) << 1) + (q & 1);
            int k0 = (ks << 4) + (j << 1);
            float w00 = Wh[n * 64 + k0] - Wc[n * 64 + k0] * (1.0f / 7.0f);
            float w01 = Wh[n * 64 + k0 + 1] - Wc[n * 64 + k0 + 1] * (1.0f / 7.0f);
            float w10 = Wh[n * 64 + k0 + 8] - Wc[n * 64 + k0 + 8] * (1.0f / 7.0f);
            float w11 = Wh[n * 64 + k0 + 9] - Wc[n * 64 + k0 + 9] * (1.0f / 7.0f);
            __nv_bfloat162 p0 = __float22bfloat162_rn(make_float2(w00, w01));
            __nv_bfloat162 p1 = __float22bfloat162_rn(make_float2(w10, w11));
            bWh[ks][nb][0] = *reinterpret_cast<uint32_t*>(&p0);
            bWh[ks][nb][1] = *reinterpret_cast<uint32_t*>(&p1);
        }
    }

    // ---- invariants ----
    const int arow = lane & 15, ahi = lane >> 4, arow7 = arow & 7;
    const int nb_ = lane >> 3, q_ = lane & 7;
    const int permL = ((nb_ >> 1) << 4) + ((q_ >> 1) << 2) + ((nb_ & 1) << 1) +
                      (q_ & 1);
    const int lrow = (c << 5) + permL;
    const uint32_t wlbase = sb + W1L + (uint32_t)(lrow << 7);
    const int lr7 = lrow & 7;
    const int brow2 = (w << 3) + (lane & 7);
    const int g2 = (lane >> 3) & 1;
    const uint32_t bb2 = (uint32_t)(brow2 << 7);
    const int b72 = brow2 & 7;
    const int b16 = tid >> 4, dc = tid & 15;
    const uint32_t so_off = (uint32_t)(b16 << 7) +
                            ((((dc >> 1) ^ (b16 & 7))) << 4) + ((dc & 1) << 3);

    const int grid = gridDim.x;
    int t = blockIdx.x;

    // ================= prologue: stage t0, s(t0), T(t0) =================
    float4 v[2][4];
    {
        const float* xt = x + (size_t)t * 8192;
        stage_ldg(xt, tid, v);
        stage_sts(sm, XH0, XL0, tid, v);
        const float4* sp = (const float4*)(xt + b16 * 512 + dc * 4);
        float4 sv = sp[0];
#pragma unroll
        for (int a = 1; a < 8; a++) {
            float4 u = sp[a * 16];
            sv.x += u.x; sv.y += u.y; sv.z += u.z; sv.w += u.w;
        }
        uint32_t h0, l0, h1, l1;
        split2(sv.x, sv.y, h0, l0);
        split2(sv.z, sv.w, h1, l1);
        *(uint2*)(sm + SH + so_off) = make_uint2(h0, h1);
        *(uint2*)(sm + SL + so_off) = make_uint2(l0, l1);
    }
    __syncthreads();
    // T(t0) -> T0
    {
        float accT[4] = {0.f, 0.f, 0.f, 0.f};
#pragma unroll
        for (int ks = 0; ks < 4; ks++) {
            uint32_t sa = (uint32_t)(arow << 7) +
                          ((((2 * ks + ahi) ^ arow7)) << 4);
            uint32_t b2a = bb2 + ((((2 * ks + g2) ^ b72)) << 4);
            uint32_t sh_[4], sl_[4], b2h[2], b2l[2];
            ldsm4(sh_, sb + SH + sa);
            ldsm2(b2h, sb + W2H + b2a);
            mma_bf16(accT, sh_, b2h[0], b2h[1]);
            ldsm2(b2l, sb + W2L + b2a);
            mma_bf16(accT, sh_, b2l[0], b2l[1]);
            ldsm4(sl_, sb + SL + sa);
            mma_bf16(accT, sl_, b2h[0], b2h[1]);
        }
        float* Tb = (float*)(sm + T0);
        int tc = (w << 3) + (j << 1);
        *(float2*)(Tb + q * TPITCH + tc) = make_float2(accT[0], accT[1]);
        *(float2*)(Tb + (q + 8) * TPITCH + tc) = make_float2(accT[2], accT[3]);
    }
    __syncthreads();

    int jb = 0;
    // ============================ main loop ============================
    for (;;) {
        int tn = t + grid;
        bool more = (tn < NTILES);
        const float* xtn = x + (size_t)tn * 8192;
        if (more) stage_ldg(xtn, tid, v);  // prefetch across main GEMM

        const uint32_t xhb = sb + ((jb & 1) ? XH1 : XH0);
        const uint32_t xlb = sb + ((jb & 1) ? XL1 : XL0);

        // ---- main GEMM: 96 HMMA ----
        float accY[2][4][4] = {};
#pragma unroll
        for (int ks = 0; ks < 4; ks++) {
            uint32_t bl0[4], bl1[4];
            ldsm4(bl0, wlbase + ((((2 * ks) ^ lr7)) << 4));
            ldsm4(bl1, wlbase + ((((2 * ks + 1) ^ lr7)) << 4));
#pragma unroll
            for (int bt = 0; bt < 2; bt++) {
                int rb = (g << 4) + (bt << 6);
                uint32_t xa = (uint32_t)((rb + arow) << 7) +
                              ((((2 * ks + ahi) ^ arow7)) << 4);
                uint32_t ah[4], al[4];
                ldsm4(ah, xhb + xa);
#pragma unroll
                for (int nb = 0; nb < 4; nb++)
                    mma_bf16(accY[bt][nb], ah, bWh[ks][nb][0], bWh[ks][nb][1]);
#pragma unroll
                for (int nb = 0; nb < 4; nb++)
                    mma_bf16(accY[bt][nb], ah, bl0[nb], bl1[nb]);
                ldsm4(al, xlb + xa);
#pragma unroll
                for (int nb = 0; nb < 4; nb++)
                    mma_bf16(accY[bt][nb], al, bWh[ks][nb][0], bWh[ks][nb][1]);
            }
        }

        // ---- epilogue: + T (prev-computed), tanh, STG.128 ----
        {
            const float* Tb = (const float*)(sm + ((jb & 1) ? T1 : T0));
#pragma unroll
            for (int bt = 0; bt < 2; bt++) {
#pragma unroll
                for (int h = 0; h < 2; h++) {
                    int bb = 2 * g + 8 * bt + h;
                    const float4* Trow = (const float4*)(
                        Tb + bb * TPITCH + (c << 5) + (j << 2));
                    int R = t * 128 + (g << 4) + (bt << 6) + (h << 3) + q;
                    float* op = out + (size_t)R * 64 + (c << 5) + (j << 2);
#pragma unroll
                    for (int m = 0; m < 2; m++) {
                        float4 tv = Trow[m * 4];
                        float4 o;
                        o.x = tanh_fast(accY[bt][2 * m][2 * h] + tv.x);
                        o.y = tanh_fast(accY[bt][2 * m][2 * h + 1] + tv.y);
                        o.z = tanh_fast(accY[bt][2 * m + 1][2 * h] + tv.z);
                        o.w = tanh_fast(accY[bt][2 * m + 1][2 * h + 1] + tv.w);
                        *(float4*)(op + m * 16) = o;
                    }
                }
            }
        }

        if (!more) break;

        // ---- phase B: stage t+1, s(t+1), T(t+1) ----
        {
            const float4* sp = (const float4*)(xtn + b16 * 512 + dc * 4);
            float4 s0 = sp[0], s1 = sp[16], s2 = sp[32], s3 = sp[48];
            float4 s4 = sp[64], s5 = sp[80], s6 = sp[96], s7 = sp[112];
            stage_sts(sm, (jb & 1) ? XH0 : XH1, (jb & 1) ? XL0 : XL1, tid, v);
            float4 sv;
            sv.x = ((s0.x + s1.x) + (s2.x + s3.x)) + ((s4.x + s5.x) + (s6.x + s7.x));
            sv.y = ((s0.y + s1.y) + (s2.y + s3.y)) + ((s4.y + s5.y) + (s6.y + s7.y));
            sv.z = ((s0.z + s1.z) + (s2.z + s3.z)) + ((s4.z + s5.z) + (s6.z + s7.z));
            sv.w = ((s0.w + s1.w) + (s2.w + s3.w)) + ((s4.w + s5.w) + (s6.w + s7.w));
            uint32_t h0, l0, h1, l1;
            split2(sv.x, sv.y, h0, l0);
            split2(sv.z, sv.w, h1, l1);
            *(uint2*)(sm + SH + so_off) = make_uint2(h0, h1);
            *(uint2*)(sm + SL + so_off) = make_uint2(l0, l1);
        }
        __syncthreads();
        {
            float accT[4] = {0.f, 0.f, 0.f, 0.f};
#pragma unroll
            for (int ks = 0; ks < 4; ks++) {
                uint32_t sa = (uint32_t)(arow << 7) +
                              ((((2 * ks + ahi) ^ arow7)) << 4);
                uint32_t b2a = bb2 + ((((2 * ks + g2) ^ b72)) << 4);
                uint32_t sh_[4], sl_[4], b2h[2], b2l[2];
                ldsm4(sh_, sb + SH + sa);
                ldsm2(b2h, sb + W2H + b2a);
                mma_bf16(accT, sh_, b2h[0], b2h[1]);
                ldsm2(b2l, sb + W2L + b2a);
                mma_bf16(accT, sh_, b2l[0], b2l[1]);
                ldsm4(sl_, sb + SL + sa);
                mma_bf16(accT, sl_, b2h[0], b2h[1]);
            }
            float* Tb = (float*)(sm + ((jb & 1) ? T0 : T1));
            int tc = (w << 3) + (j << 1);
            *(float2*)(Tb + q * TPITCH + tc) = make_float2(accT[0], accT[1]);
            *(float2*)(Tb + (q + 8) * TPITCH + tc) =
                make_float2(accT[2], accT[3]);
        }
        __syncthreads();

        t = tn;
        ++jb;
    }
}

extern "C" void kernel_launch(void* const* d_in, const int* in_sizes, int n_in,
                              void* d_out, int out_size) {
    const float* x  = (const float*)d_in[0];
    const float* Wh = (const float*)d_in[1];
    const float* Wc = (const float*)d_in[2];
    float* out = (float*)d_out;

    int dev = 0, sms = 148;
    cudaGetDevice(&dev);
    cudaDeviceGetAttribute(&sms, cudaDevAttrMultiProcessorCount, dev);

    cudaFuncSetAttribute(comm_v6, cudaFuncAttributeMaxDynamicSharedMemorySize,
                         SMEM_SZ);
    comm_v6<<<2 * sms, 256, SMEM_SZ>>>(x, Wh, Wc, out);
}

// round 8
// speedup vs baseline: 1.1906x; 1.1906x over previous
#include <cuda_runtime.h>
#include <cuda_bf16.h>
#include <cstdint>

// out = tanh( Xa @ W1'^T + T[b] ),  T = s @ W2^T,  s[b] = sum_a x[b,a,:]
// W1' = Wh - Wc/7, W2 = Wc/7. Split-bf16 HMMA (xh*Wh + xh*Wl + xl*Wh).
// 128-row tiles. Phase A: Y-GEMM(t) + convert(t+1 from global) + epilogue(t).
// Phase B: T-GEMM(t+1) only (W2 frags in regs). 2 bars/tile, L2 prefetch
// one tile ahead, XH/XL and T double-buffered. No fp32 smem stage.

#define NTILES 4096
#define TPITCH 68

#define XH0 0
#define XL0 16384
#define XH1 32768
#define XL1 49152
#define W1L 65536
#define SH  73728
#define SL  75776
#define T0  77824
#define T1  82176
#define SMEM_SZ 86528

__device__ __forceinline__ uint32_t smem_u32(const void* p) {
    uint32_t a;
    asm("{ .reg .u64 t; cvta.to.shared.u64 t, %1; cvt.u32.u64 %0, t; }"
        : "=r"(a) : "l"(p));
    return a;
}

__device__ __forceinline__ void mma_bf16(float* c, const uint32_t* a,
                                         uint32_t b0, uint32_t b1) {
    asm volatile(
        "mma.sync.aligned.m16n8k16.row.col.f32.bf16.bf16.f32 "
        "{%0,%1,%2,%3}, {%4,%5,%6,%7}, {%8,%9}, {%0,%1,%2,%3};"
        : "+f"(c[0]), "+f"(c[1]), "+f"(c[2]), "+f"(c[3])
        : "r"(a[0]), "r"(a[1]), "r"(a[2]), "r"(a[3]), "r"(b0), "r"(b1));
}

__device__ __forceinline__ void ldsm4(uint32_t* r, uint32_t addr) {
    asm volatile(
        "ldmatrix.sync.aligned.m8n8.x4.shared.b16 {%0,%1,%2,%3}, [%4];"
        : "=r"(r[0]), "=r"(r[1]), "=r"(r[2]), "=r"(r[3]) : "r"(addr));
}

__device__ __forceinline__ float tanh_fast(float y) {
    float r;
    asm("tanh.approx.f32 %0, %1;" : "=f"(r) : "f"(y));
    return r;
}

__device__ __forceinline__ void split2(float a, float b, uint32_t& h,
                                       uint32_t& l) {
    __nv_bfloat162 hb = __float22bfloat162_rn(make_float2(a, b));
    float2 g = __bfloat1622float2(hb);
    __nv_bfloat162 lb = __float22bfloat162_rn(make_float2(a - g.x, b - g.y));
    h = *reinterpret_cast<uint32_t*>(&hb);
    l = *reinterpret_cast<uint32_t*>(&lb);
}

// Convert one 128-row tile from global fp32 to split-bf16 smem; also emit s.
__device__ __forceinline__ void convert_tile(const float* xt, char* sm,
                                             uint32_t xh, uint32_t xl,
                                             int b16, int dc,
                                             uint32_t so_off) {
    const float4* sp = (const float4*)(xt + b16 * 512) + dc;
    float sx = 0.f, sy = 0.f, sz = 0.f, sw = 0.f;
#pragma unroll
    for (int a = 0; a < 8; a++) {
        float4 v = sp[a * 16];
        sx += v.x; sy += v.y; sz += v.z; sw += v.w;
        uint32_t h0, l0, h1, l1;
        split2(v.x, v.y, h0, l0);
        split2(v.z, v.w, h1, l1);
        int r = b16 * 8 + a;
        uint32_t ro = (uint32_t)(r << 7) +
                      ((((dc >> 1) ^ (r & 7))) << 4) + ((dc & 1) << 3);
        *(uint2*)(sm + xh + ro) = make_uint2(h0, h1);
        *(uint2*)(sm + xl + ro) = make_uint2(l0, l1);
    }
    uint32_t h0, l0, h1, l1;
    split2(sx, sy, h0, l0);
    split2(sz, sw, h1, l1);
    *(uint2*)(sm + SH + so_off) = make_uint2(h0, h1);
    *(uint2*)(sm + SL + so_off) = make_uint2(l0, l1);
}

__global__ void __launch_bounds__(256, 2)
comm_v8(const float* __restrict__ x, const float* __restrict__ Wh,
        const float* __restrict__ Wc, float* __restrict__ out) {
    extern __shared__ char sm[];
    const uint32_t sb = smem_u32(sm);

    const int tid = threadIdx.x;
    const int w = tid >> 5;
    const int lane = tid & 31;
    const int g = w >> 1, c = w & 1;
    const int q = lane >> 2, j = lane & 3;

    // ---- W1'-lo smem tile (swizzled K-major) ----
    for (int i = tid; i < 4096; i += 256) {
        int n = i >> 6, k = i & 63;
        float cc = Wc[i] * (1.0f / 7.0f);
        float w1 = Wh[i] - cc;
        uint32_t off =
            (uint32_t)(n << 7) + ((((k >> 3) ^ (n & 7))) << 4) + ((k & 7) << 1);
        __nv_bfloat16 w1h = __float2bfloat16(w1);
        *(__nv_bfloat16*)(sm + W1L + off) =
            __float2bfloat16(w1 - __bfloat162float(w1h));
    }

    // ---- W1'-hi B fragments in registers, permuted logical columns ----
    uint32_t bWh[4][4][2];
#pragma unroll
    for (int ks = 0; ks < 4; ks++) {
#pragma unroll
        for (int nb = 0; nb < 4; nb++) {
            int n = (c << 5) + ((nb >> 1) << 4) + ((q >> 1) << 2) +
                    ((nb & 1) << 1) + (q & 1);
            int k0 = (ks << 4) + (j << 1);
            float w00 = Wh[n * 64 + k0] - Wc[n * 64 + k0] * (1.0f / 7.0f);
            float w01 = Wh[n * 64 + k0 + 1] - Wc[n * 64 + k0 + 1] * (1.0f / 7.0f);
            float w10 = Wh[n * 64 + k0 + 8] - Wc[n * 64 + k0 + 8] * (1.0f / 7.0f);
            float w11 = Wh[n * 64 + k0 + 9] - Wc[n * 64 + k0 + 9] * (1.0f / 7.0f);
            __nv_bfloat162 p0 = __float22bfloat162_rn(make_float2(w00, w01));
            __nv_bfloat162 p1 = __float22bfloat162_rn(make_float2(w10, w11));
            bWh[ks][nb][0] = *reinterpret_cast<uint32_t*>(&p0);
            bWh[ks][nb][1] = *reinterpret_cast<uint32_t*>(&p1);
        }
    }

    // ---- W2 8-col slice B fragments (hi+lo) in registers, loop-invariant ----
    uint32_t b2h[4][2], b2l[4][2];
#pragma unroll
    for (int ks = 0; ks < 4; ks++) {
        int n = (w << 3) + q;
        int k0 = (ks << 4) + (j << 1);
        float v00 = Wc[n * 64 + k0] * (1.0f / 7.0f);
        float v01 = Wc[n * 64 + k0 + 1] * (1.0f / 7.0f);
        float v10 = Wc[n * 64 + k0 + 8] * (1.0f / 7.0f);
        float v11 = Wc[n * 64 + k0 + 9] * (1.0f / 7.0f);
        uint32_t h0, l0, h1, l1;
        split2(v00, v01, h0, l0);
        split2(v10, v11, h1, l1);
        b2h[ks][0] = h0; b2h[ks][1] = h1;
        b2l[ks][0] = l0; b2l[ks][1] = l1;
    }

    // ---- invariants ----
    const int arow = lane & 15, ahi = lane >> 4, arow7 = arow & 7;
    const int nb_ = lane >> 3, q_ = lane & 7;
    const int permL = ((nb_ >> 1) << 4) + ((q_ >> 1) << 2) + ((nb_ & 1) << 1) +
                      (q_ & 1);
    const int lrow = (c << 5) + permL;
    const uint32_t wlbase = sb + W1L + (uint32_t)(lrow << 7);
    const int lr7 = lrow & 7;
    const int b16 = tid >> 4, dc = tid & 15;
    const uint32_t so_off = (uint32_t)(b16 << 7) +
                            ((((dc >> 1) ^ (b16 & 7))) << 4) + ((dc & 1) << 3);

    const int grid = gridDim.x;
    int t = blockIdx.x;
    int p = 0;

    // ================= prologue: convert(t0), T(t0) =================
    convert_tile(x + (size_t)t * 8192, sm, XH0, XL0, b16, dc, so_off);
    __syncthreads();
    {
        float accT[4] = {0.f, 0.f, 0.f, 0.f};
#pragma unroll
        for (int ks = 0; ks < 4; ks++) {
            uint32_t sa = (uint32_t)(arow << 7) +
                          ((((2 * ks + ahi) ^ arow7)) << 4);
            uint32_t sh_[4], sl_[4];
            ldsm4(sh_, sb + SH + sa);
            mma_bf16(accT, sh_, b2h[ks][0], b2h[ks][1]);
            mma_bf16(accT, sh_, b2l[ks][0], b2l[ks][1]);
            ldsm4(sl_, sb + SL + sa);
            mma_bf16(accT, sl_, b2h[ks][0], b2h[ks][1]);
        }
        float* Tb = (float*)(sm + T0);
        int tc = (w << 3) + (j << 1);
        *(float2*)(Tb + q * TPITCH + tc) = make_float2(accT[0], accT[1]);
        *(float2*)(Tb + (q + 8) * TPITCH + tc) = make_float2(accT[2], accT[3]);
        if (t + grid < NTILES) {
            const char* pp =
                (const char*)(x + (size_t)(t + grid) * 8192) + tid * 128;
            asm volatile("prefetch.global.L2 [%0];" :: "l"(pp));
        }
    }
    __syncthreads();

    // ============================ main loop ============================
    for (;;) {
        int tn = t + grid;
        bool more = (tn < NTILES);
        const uint32_t xhb = sb + (p ? XH1 : XH0);
        const uint32_t xlb = sb + (p ? XL1 : XL0);

        // ---- Y-GEMM(t): 96 HMMA, W1h in regs, W1l streamed ----
        float accY[2][4][4] = {};
#pragma unroll
        for (int ks = 0; ks < 4; ks++) {
            uint32_t bl0[4], bl1[4];
            ldsm4(bl0, wlbase + ((((2 * ks) ^ lr7)) << 4));
            ldsm4(bl1, wlbase + ((((2 * ks + 1) ^ lr7)) << 4));
#pragma unroll
            for (int bt = 0; bt < 2; bt++) {
                int rb = (g << 4) + (bt << 6);
                uint32_t xa = (uint32_t)((rb + arow) << 7) +
                              ((((2 * ks + ahi) ^ arow7)) << 4);
                uint32_t ah[4], al[4];
                ldsm4(ah, xhb + xa);
#pragma unroll
                for (int nb = 0; nb < 4; nb++)
                    mma_bf16(accY[bt][nb], ah, bWh[ks][nb][0], bWh[ks][nb][1]);
#pragma unroll
                for (int nb = 0; nb < 4; nb++)
                    mma_bf16(accY[bt][nb], ah, bl0[nb], bl1[nb]);
                ldsm4(al, xlb + xa);
#pragma unroll
                for (int nb = 0; nb < 4; nb++)
                    mma_bf16(accY[bt][nb], al, bWh[ks][nb][0], bWh[ks][nb][1]);
            }
        }

        // ---- convert(t+1) from global (L2-prefetched), into XH/XL[1-p] ----
        if (more)
            convert_tile(x + (size_t)tn * 8192, sm, p ? XH0 : XH1,
                         p ? XL0 : XL1, b16, dc, so_off);

        // ---- epilogue(t): + T[p], tanh, STG.128 ----
        {
            const float* Tb = (const float*)(sm + (p ? T1 : T0));
#pragma unroll
            for (int bt = 0; bt < 2; bt++) {
#pragma unroll
                for (int h = 0; h < 2; h++) {
                    int bb = 2 * g + 8 * bt + h;
                    const float4* Trow = (const float4*)(
                        Tb + bb * TPITCH + (c << 5) + (j << 2));
                    int R = t * 128 + (g << 4) + (bt << 6) + (h << 3) + q;
                    float* op = out + (size_t)R * 64 + (c << 5) + (j << 2);
#pragma unroll
                    for (int m = 0; m < 2; m++) {
                        float4 tv = Trow[m * 4];
                        float4 o;
                        o.x = tanh_fast(accY[bt][2 * m][2 * h] + tv.x);
                        o.y = tanh_fast(accY[bt][2 * m][2 * h + 1] + tv.y);
                        o.z = tanh_fast(accY[bt][2 * m + 1][2 * h] + tv.z);
                        o.w = tanh_fast(accY[bt][2 * m + 1][2 * h + 1] + tv.w);
                        *(float4*)(op + m * 16) = o;
                    }
                }
            }
        }

        if (!more) break;
        __syncthreads();

        // ---- phase B: T-GEMM(t+1) -> T[1-p]; prefetch(t+2) ----
        {
            float accT[4] = {0.f, 0.f, 0.f, 0.f};
#pragma unroll
            for (int ks = 0; ks < 4; ks++) {
                uint32_t sa = (uint32_t)(arow << 7) +
                              ((((2 * ks + ahi) ^ arow7)) << 4);
                uint32_t sh_[4], sl_[4];
                ldsm4(sh_, sb + SH + sa);
                mma_bf16(accT, sh_, b2h[ks][0], b2h[ks][1]);
                mma_bf16(accT, sh_, b2l[ks][0], b2l[ks][1]);
                ldsm4(sl_, sb + SL + sa);
                mma_bf16(accT, sl_, b2h[ks][0], b2h[ks][1]);
            }
            float* Tb = (float*)(sm + (p ? T0 : T1));
            int tc = (w << 3) + (j << 1);
            *(float2*)(Tb + q * TPITCH + tc) = make_float2(accT[0], accT[1]);
            *(float2*)(Tb + (q + 8) * TPITCH + tc) =
                make_float2(accT[2], accT[3]);
            if (tn + grid < NTILES) {
                const char* pp =
                    (const char*)(x + (size_t)(tn + grid) * 8192) + tid * 128;
                asm volatile("prefetch.global.L2 [%0];" :: "l"(pp));
            }
        }
        __syncthreads();

        t = tn;
        p ^= 1;
    }
}

extern "C" void kernel_launch(void* const* d_in, const int* in_sizes, int n_in,
                              void* d_out, int out_size) {
    const float* x  = (const float*)d_in[0];
    const float* Wh = (const float*)d_in[1];
    const float* Wc = (const float*)d_in[2];
    float* out = (float*)d_out;

    int dev = 0, sms = 148;
    cudaGetDevice(&dev);
    cudaDeviceGetAttribute(&sms, cudaDevAttrMultiProcessorCount, dev);

    cudaFuncSetAttribute(comm_v8, cudaFuncAttributeMaxDynamicSharedMemorySize,
                         SMEM_SZ);
    comm_v8<<<2 * sms, 256, SMEM_SZ>>>(x, Wh, Wc, out);
}

// round 9
// speedup vs baseline: 1.6250x; 1.3648x over previous
#include <cuda_runtime.h>
#include <cuda_fp16.h>
#include <cstdint>

// out = tanh( Xa @ [W1'|W2]^T  with agent-sum on the W2 half ), fp16 single
// product, fp32 accum. Xa: [524288, 64]. W1' = Wh - Wc/7, W2 = Wc/7.
// 64-row tiles, 8 warps: (rh = w>>2) 16-row group x (cq = w&3) 16-col slice
// of both W1' and W2. One __syncthreads per tile (disjoint double buffer).

#define NTILES 8192  // 524288 / 64

__device__ __forceinline__ uint32_t smem_u32(const void* p) {
    uint32_t a;
    asm("{ .reg .u64 t; cvta.to.shared.u64 t, %1; cvt.u32.u64 %0, t; }"
        : "=r"(a) : "l"(p));
    return a;
}

__device__ __forceinline__ uint32_t pack_h2(float a, float b) {
    __half2 t = __float22half2_rn(make_float2(a, b));
    return *reinterpret_cast<uint32_t*>(&t);
}

__device__ __forceinline__ void mma_fp16(float* c, const uint32_t* a,
                                         uint32_t b0, uint32_t b1) {
    asm volatile(
        "mma.sync.aligned.m16n8k16.row.col.f32.f16.f16.f32 "
        "{%0,%1,%2,%3}, {%4,%5,%6,%7}, {%8,%9}, {%0,%1,%2,%3};"
        : "+f"(c[0]), "+f"(c[1]), "+f"(c[2]), "+f"(c[3])
        : "r"(a[0]), "r"(a[1]), "r"(a[2]), "r"(a[3]), "r"(b0), "r"(b1));
}

__device__ __forceinline__ void ldsm4(uint32_t* r, uint32_t addr) {
    asm volatile(
        "ldmatrix.sync.aligned.m8n8.x4.shared.b16 {%0,%1,%2,%3}, [%4];"
        : "=r"(r[0]), "=r"(r[1]), "=r"(r[2]), "=r"(r[3]) : "r"(addr));
}

__device__ __forceinline__ float tanh_fast(float y) {
    float r;
    asm("tanh.approx.f32 %0, %1;" : "=f"(r) : "f"(y));
    return r;
}

__global__ void __launch_bounds__(256, 2)
comm_fp16(const float* __restrict__ x, const float* __restrict__ Wh,
          const float* __restrict__ Wc, float* __restrict__ out) {
    __shared__ __align__(16) char xs[2][8192];  // fp16 tile, double buffer

    const int tid = threadIdx.x;
    const int w = tid >> 5, lane = tid & 31;
    const int cq = w & 3, rh = w >> 2;
    const int q = lane >> 2, j = lane & 3;

    // ---- B fragments (fp16) in registers: bF[mat][ks][nb][2], 32 regs ----
    uint32_t bF[2][4][2][2];
#pragma unroll
    for (int mat = 0; mat < 2; mat++) {
#pragma unroll
        for (int ks = 0; ks < 4; ks++) {
#pragma unroll
            for (int nb = 0; nb < 2; nb++) {
                int n = cq * 16 + nb * 8 + q;
                int i00 = n * 64 + ks * 16 + j * 2;
                int i10 = i00 + 8;
                float w00, w01, w10, w11;
                if (mat == 0) {
                    w00 = Wh[i00] - Wc[i00] * (1.0f / 7.0f);
                    w01 = Wh[i00 + 1] - Wc[i00 + 1] * (1.0f / 7.0f);
                    w10 = Wh[i10] - Wc[i10] * (1.0f / 7.0f);
                    w11 = Wh[i10 + 1] - Wc[i10 + 1] * (1.0f / 7.0f);
                } else {
                    w00 = Wc[i00] * (1.0f / 7.0f);
                    w01 = Wc[i00 + 1] * (1.0f / 7.0f);
                    w10 = Wc[i10] * (1.0f / 7.0f);
                    w11 = Wc[i10 + 1] * (1.0f / 7.0f);
                }
                bF[mat][ks][nb][0] = pack_h2(w00, w01);
                bF[mat][ks][nb][1] = pack_h2(w10, w11);
            }
        }
    }

    // ---- invariants ----
    const uint32_t sb = smem_u32(xs);
    const int arow = lane & 15, ahi = lane >> 4;
    uint32_t abase[2];
    int ar7[2];
#pragma unroll
    for (int bt = 0; bt < 2; bt++) {
        int r = rh * 16 + bt * 32 + arow;
        abase[bt] = (uint32_t)(r << 7);
        ar7[bt] = r & 7;
    }
    const int srow = tid >> 2, sc = tid & 3;
    const uint32_t s0off =
        (uint32_t)(srow << 7) + ((((sc << 1) ^ (srow & 7))) << 4);
    const uint32_t s1off =
        (uint32_t)(srow << 7) + (((((sc << 1) + 1) ^ (srow & 7))) << 4);

    const int grid = gridDim.x;
    int t = blockIdx.x, p = 0;

    // preload first tile: thread = (row tid>>2, 16 floats at col (tid&3)*16)
    float4 v[4];
    {
        const float4* xp =
            (const float4*)(x + (size_t)t * 4096 + srow * 64 + sc * 16);
        v[0] = xp[0]; v[1] = xp[1]; v[2] = xp[2]; v[3] = xp[3];
    }

    for (;;) {
        // ---- convert to fp16, STS into buffer p ----
        {
            char* buf = xs[p];
            uint4 h0 = make_uint4(pack_h2(v[0].x, v[0].y),
                                  pack_h2(v[0].z, v[0].w),
                                  pack_h2(v[1].x, v[1].y),
                                  pack_h2(v[1].z, v[1].w));
            uint4 h1 = make_uint4(pack_h2(v[2].x, v[2].y),
                                  pack_h2(v[2].z, v[2].w),
                                  pack_h2(v[3].x, v[3].y),
                                  pack_h2(v[3].z, v[3].w));
            *(uint4*)(buf + s0off) = h0;
            *(uint4*)(buf + s1off) = h1;
        }
        __syncthreads();

        int tn = t + grid;
        bool more = (tn < NTILES);
        if (more) {  // prefetch next tile behind MMAs
            const float4* xp =
                (const float4*)(x + (size_t)tn * 4096 + srow * 64 + sc * 16);
            v[0] = xp[0]; v[1] = xp[1]; v[2] = xp[2]; v[3] = xp[3];
        }

        // ---- GEMM: 8 ldsm4 + 32 HMMA ----
        float acc[2][2][2][4] = {};  // [bt][mat][nb][4]
        const uint32_t xb = sb + (p ? 8192u : 0u);
#pragma unroll
        for (int ks = 0; ks < 4; ks++) {
#pragma unroll
            for (int bt = 0; bt < 2; bt++) {
                uint32_t a[4];
                ldsm4(a, xb + abase[bt] +
                             ((((ks << 1) + ahi) ^ ar7[bt]) << 4));
#pragma unroll
                for (int mat = 0; mat < 2; mat++)
#pragma unroll
                    for (int nb = 0; nb < 2; nb++)
                        mma_fp16(acc[bt][mat][nb], a, bF[mat][ks][nb][0],
                                 bF[mat][ks][nb][1]);
            }
        }

        // ---- epilogue: agent-sum (shfl over lane bits 2..4), tanh, STG ----
#pragma unroll
        for (int bt = 0; bt < 2; bt++) {
            int R0 = t * 64 + rh * 16 + bt * 32 + q;
#pragma unroll
            for (int nb = 0; nb < 2; nb++) {
                float s0 = acc[bt][1][nb][0], s1 = acc[bt][1][nb][1];
                float s2 = acc[bt][1][nb][2], s3 = acc[bt][1][nb][3];
#pragma unroll
                for (int m = 4; m <= 16; m <<= 1) {
                    s0 += __shfl_xor_sync(0xffffffffu, s0, m);
                    s1 += __shfl_xor_sync(0xffffffffu, s1, m);
                    s2 += __shfl_xor_sync(0xffffffffu, s2, m);
                    s3 += __shfl_xor_sync(0xffffffffu, s3, m);
                }
                int cc = cq * 16 + nb * 8 + j * 2;
                *(float2*)(out + (size_t)R0 * 64 + cc) =
                    make_float2(tanh_fast(acc[bt][0][nb][0] + s0),
                                tanh_fast(acc[bt][0][nb][1] + s1));
                *(float2*)(out + (size_t)(R0 + 8) * 64 + cc) =
                    make_float2(tanh_fast(acc[bt][0][nb][2] + s2),
                                tanh_fast(acc[bt][0][nb][3] + s3));
            }
        }

        if (!more) break;
        t = tn;
        p ^= 1;
    }
}

extern "C" void kernel_launch(void* const* d_in, const int* in_sizes, int n_in,
                              void* d_out, int out_size) {
    const float* x  = (const float*)d_in[0];
    const float* Wh = (const float*)d_in[1];
    const float* Wc = (const float*)d_in[2];
    float* out = (float*)d_out;

    int dev = 0, sms = 148;
    cudaGetDevice(&dev);
    cudaDeviceGetAttribute(&sms, cudaDevAttrMultiProcessorCount, dev);

    comm_fp16<<<2 * sms, 256>>>(x, Wh, Wc, out);
}

// round 10
// speedup vs baseline: 1.9365x; 1.1917x over previous
#include <cuda_runtime.h>
#include <cuda_fp16.h>
#include <cstdint>

// out = tanh( Xa @ W1'^T + T[b] ),  T = s @ W2^T,  s[b] = sum_a x[b,a,:]
// W1' = Wh - Wc/7, W2 = Wc/7. fp16 single-product HMMA, fp32 accum.
// 64-row tiles (= 8 batch rows). Convert phase: warp w owns batch row w,
// lane owns one k-pair across all 8 agents -> s is a free in-register sum.
// T-GEMM: 4 MMA/warp (8 e-cols), m16 frag with zeroed upper rows.
// Main GEMM: 16 MMA/warp (W1' only), B-frags in regs, permuted cols for
// STG.128 epilogue. No shuffles anywhere.

#define NTILES 8192  // 524288 / 64

#define X0 0
#define X1 8192
#define S0 16384
#define S1 17408
#define TB0 18432
#define TB1 20480
#define SMEM_SZ 22528

__device__ __forceinline__ uint32_t smem_u32(const void* p) {
    uint32_t a;
    asm("{ .reg .u64 t; cvta.to.shared.u64 t, %1; cvt.u32.u64 %0, t; }"
        : "=r"(a) : "l"(p));
    return a;
}

__device__ __forceinline__ uint32_t pack_h2(float a, float b) {
    __half2 t = __float22half2_rn(make_float2(a, b));
    return *reinterpret_cast<uint32_t*>(&t);
}

__device__ __forceinline__ void mma_fp16(float* c, const uint32_t* a,
                                         uint32_t b0, uint32_t b1) {
    asm volatile(
        "mma.sync.aligned.m16n8k16.row.col.f32.f16.f16.f32 "
        "{%0,%1,%2,%3}, {%4,%5,%6,%7}, {%8,%9}, {%0,%1,%2,%3};"
        : "+f"(c[0]), "+f"(c[1]), "+f"(c[2]), "+f"(c[3])
        : "r"(a[0]), "r"(a[1]), "r"(a[2]), "r"(a[3]), "r"(b0), "r"(b1));
}

__device__ __forceinline__ void ldsm4(uint32_t* r, uint32_t addr) {
    asm volatile(
        "ldmatrix.sync.aligned.m8n8.x4.shared.b16 {%0,%1,%2,%3}, [%4];"
        : "=r"(r[0]), "=r"(r[1]), "=r"(r[2]), "=r"(r[3]) : "r"(addr));
}

__device__ __forceinline__ void ldsm2(uint32_t* r, uint32_t addr) {
    asm volatile(
        "ldmatrix.sync.aligned.m8n8.x2.shared.b16 {%0,%1}, [%2];"
        : "=r"(r[0]), "=r"(r[1]) : "r"(addr));
}

__device__ __forceinline__ float tanh_fast(float y) {
    float r;
    asm("tanh.approx.f32 %0, %1;" : "=f"(r) : "f"(y));
    return r;
}

__global__ void __launch_bounds__(256, 2)
comm_v9(const float* __restrict__ x, const float* __restrict__ Wh,
        const float* __restrict__ Wc, float* __restrict__ out) {
    __shared__ __align__(16) char sm[SMEM_SZ];
    const uint32_t sb = smem_u32(sm);

    const int tid = threadIdx.x;
    const int w = tid >> 5, lane = tid & 31;
    const int cq = w & 3, rh = w >> 2;
    const int q = lane >> 2, j = lane & 3;

    // ---- W1' B-frags in regs (16), logical cols permuted so thread j
    // owns 4 consecutive cols: L = cq*16 + 4*(q>>1)+2nb+(q&1) ----
    uint32_t bW[4][2][2];
#pragma unroll
    for (int ks = 0; ks < 4; ks++) {
#pragma unroll
        for (int nb = 0; nb < 2; nb++) {
            int n = cq * 16 + ((q >> 1) << 2) + (nb << 1) + (q & 1);
            int i00 = n * 64 + ks * 16 + j * 2;
            int i10 = i00 + 8;
            float w00 = Wh[i00] - Wc[i00] * (1.0f / 7.0f);
            float w01 = Wh[i00 + 1] - Wc[i00 + 1] * (1.0f / 7.0f);
            float w10 = Wh[i10] - Wc[i10] * (1.0f / 7.0f);
            float w11 = Wh[i10 + 1] - Wc[i10 + 1] * (1.0f / 7.0f);
            bW[ks][nb][0] = pack_h2(w00, w01);
            bW[ks][nb][1] = pack_h2(w10, w11);
        }
    }
    // ---- W2 B-frags for T-GEMM (8 regs): warp covers e-cols w*8..w*8+7 ----
    uint32_t bT[4][2];
#pragma unroll
    for (int ks = 0; ks < 4; ks++) {
        int n = (w << 3) + q;
        int i00 = n * 64 + ks * 16 + j * 2;
        int i10 = i00 + 8;
        bT[ks][0] = pack_h2(Wc[i00] * (1.0f / 7.0f), Wc[i00 + 1] * (1.0f / 7.0f));
        bT[ks][1] = pack_h2(Wc[i10] * (1.0f / 7.0f), Wc[i10 + 1] * (1.0f / 7.0f));
    }

    // ---- main ldsm invariants ----
    const int arow = lane & 15, ahi = lane >> 4;
    uint32_t abase[2];
    int ar7[2];
#pragma unroll
    for (int bt = 0; bt < 2; bt++) {
        int r = rh * 16 + bt * 32 + arow;
        abase[bt] = (uint32_t)(r << 7);
        ar7[bt] = r & 7;
    }
    // convert STS invariant pieces (lane = k-pair index 0..31)
    const uint32_t cgr = (uint32_t)(lane >> 2);
    const uint32_t cof = (uint32_t)((lane & 3) << 2);
    // s-ldsm address (lanes 0..15 meaningful)
    const int tl = lane & 15, srow = tl & 7, shi = tl >> 3;

    const int grid = gridDim.x;
    int t = blockIdx.x, p = 0;

    // preload tile t: v[a] = x[t*64 + w*8 + a, 2*lane .. 2*lane+1]
    float2 v[8];
    {
        const float2* xp = (const float2*)(x + (size_t)t * 4096 + w * 512) + lane;
#pragma unroll
        for (int a = 0; a < 8; a++) v[a] = xp[a * 32];
    }

    for (;;) {
        // ---- convert + s (in-register fp32 sum, no shuffles) ----
        {
            char* xb = sm + (p ? X1 : X0);
            char* sf = sm + (p ? S1 : S0);
            float sx = 0.f, sy = 0.f;
#pragma unroll
            for (int a = 0; a < 8; a++) {
                sx += v[a].x;
                sy += v[a].y;
                int r = (w << 3) + a;
                uint32_t ro = (uint32_t)(r << 7) +
                              (((cgr ^ (uint32_t)(r & 7))) << 4) + cof;
                *(uint32_t*)(xb + ro) = pack_h2(v[a].x, v[a].y);
            }
            uint32_t so = (uint32_t)(w << 7) +
                          (((cgr ^ (uint32_t)(w & 7))) << 4) + cof;
            *(uint32_t*)(sf + so) = pack_h2(sx, sy);
        }
        int tn = t + grid;
        bool more = (tn < NTILES);
        if (more) {  // prefetch next tile (hidden behind syncs + GEMMs)
            const float2* xp =
                (const float2*)(x + (size_t)tn * 4096 + w * 512) + lane;
#pragma unroll
            for (int a = 0; a < 8; a++) v[a] = xp[a * 32];
        }
        __syncthreads();

        // ---- T-GEMM: T[b, w*8..w*8+7] = s @ W2^T, 4 MMA ----
        {
            float accT[4] = {0.f, 0.f, 0.f, 0.f};
            const uint32_t sbase = sb + (p ? S1 : S0);
#pragma unroll
            for (int ks = 0; ks < 4; ks++) {
                uint32_t r2[2];
                ldsm2(r2, sbase + (uint32_t)(srow << 7) +
                              ((((2 * ks + shi) ^ srow)) << 4));
                uint32_t a4[4] = {r2[0], 0u, r2[1], 0u};  // rows 8-15 zero
                mma_fp16(accT, a4, bT[ks][0], bT[ks][1]);
            }
            float* Tb = (float*)(sm + (p ? TB1 : TB0));
            *(float2*)(Tb + q * 64 + (w << 3) + (j << 1)) =
                make_float2(accT[0], accT[1]);
        }
        __syncthreads();

        // ---- main GEMM: 16 MMA (W1' only) ----
        float acc[2][2][4] = {};
        const uint32_t xbb = sb + (p ? X1 : X0);
#pragma unroll
        for (int ks = 0; ks < 4; ks++) {
#pragma unroll
            for (int bt = 0; bt < 2; bt++) {
                uint32_t a[4];
                ldsm4(a, xbb + abase[bt] +
                             ((((ks << 1) + ahi) ^ ar7[bt]) << 4));
#pragma unroll
                for (int nb = 0; nb < 2; nb++)
                    mma_fp16(acc[bt][nb], a, bW[ks][nb][0], bW[ks][nb][1]);
            }
        }

        // ---- epilogue: +T (broadcast LDS.128), tanh, STG.128 ----
        {
            const float* Tb = (const float*)(sm + (p ? TB1 : TB0));
            int cc = cq * 16 + (j << 2);
#pragma unroll
            for (int bt = 0; bt < 2; bt++) {
                int bloc = 2 * rh + 4 * bt;
                int R0 = t * 64 + rh * 16 + bt * 32 + q;
                float4 t0 = *(const float4*)(Tb + bloc * 64 + cc);
                float4 t1 = *(const float4*)(Tb + (bloc + 1) * 64 + cc);
                float4 o0, o1;
                o0.x = tanh_fast(acc[bt][0][0] + t0.x);
                o0.y = tanh_fast(acc[bt][0][1] + t0.y);
                o0.z = tanh_fast(acc[bt][1][0] + t0.z);
                o0.w = tanh_fast(acc[bt][1][1] + t0.w);
                o1.x = tanh_fast(acc[bt][0][2] + t1.x);
                o1.y = tanh_fast(acc[bt][0][3] + t1.y);
                o1.z = tanh_fast(acc[bt][1][2] + t1.z);
                o1.w = tanh_fast(acc[bt][1][3] + t1.w);
                *(float4*)(out + (size_t)R0 * 64 + cc) = o0;
                *(float4*)(out + (size_t)(R0 + 8) * 64 + cc) = o1;
            }
        }

        if (!more) break;
        t = tn;
        p ^= 1;
    }
}

extern "C" void kernel_launch(void* const* d_in, const int* in_sizes, int n_in,
                              void* d_out, int out_size) {
    const float* x  = (const float*)d_in[0];
    const float* Wh = (const float*)d_in[1];
    const float* Wc = (const float*)d_in[2];
    float* out = (float*)d_out;

    int dev = 0, sms = 148;
    cudaGetDevice(&dev);
    cudaDeviceGetAttribute(&sms, cudaDevAttrMultiProcessorCount, dev);

    comm_v9<<<2 * sms, 256>>>(x, Wh, Wc, out);
}

// round 11
// speedup vs baseline: 1.9387x; 1.0012x over previous
#include <cuda_runtime.h>
#include <cuda_fp16.h>
#include <cstdint>

// out = tanh( Xa @ W1'^T + T[b] ),  T = s @ W2^T,  s[b] = sum_a x[b,a,:]
// W1' = Wh - Wc/7, W2 = Wc/7. fp16 single-product HMMA, fp32 accum.
// 128-row tiles (= 16 batch rows). Warp (g=w>>1, c=w&1): rows
// {g*16+bt*64}, cols c*32..c*32+31 (2x A redundancy, was 4x).
// Convert: LDG.128, lane>>4 picks one of 2 batch rows/warp; s = free
// in-register fp32 sum. T-GEMM: full m16 frag, 4 MMA/warp.
// Permuted B columns for pure STG.128 epilogue. No shuffles.

#define NTILES 4096  // 524288 / 128

#define X0 0
#define X1 16384
#define S0 32768
#define S1 34816
#define T0 36864
#define T1 40960
#define SMEM_SZ 45056

__device__ __forceinline__ uint32_t smem_u32(const void* p) {
    uint32_t a;
    asm("{ .reg .u64 t; cvta.to.shared.u64 t, %1; cvt.u32.u64 %0, t; }"
        : "=r"(a) : "l"(p));
    return a;
}

__device__ __forceinline__ uint32_t pack_h2(float a, float b) {
    __half2 t = __float22half2_rn(make_float2(a, b));
    return *reinterpret_cast<uint32_t*>(&t);
}

__device__ __forceinline__ void mma_fp16(float* c, const uint32_t* a,
                                         uint32_t b0, uint32_t b1) {
    asm volatile(
        "mma.sync.aligned.m16n8k16.row.col.f32.f16.f16.f32 "
        "{%0,%1,%2,%3}, {%4,%5,%6,%7}, {%8,%9}, {%0,%1,%2,%3};"
        : "+f"(c[0]), "+f"(c[1]), "+f"(c[2]), "+f"(c[3])
        : "r"(a[0]), "r"(a[1]), "r"(a[2]), "r"(a[3]), "r"(b0), "r"(b1));
}

__device__ __forceinline__ void ldsm4(uint32_t* r, uint32_t addr) {
    asm volatile(
        "ldmatrix.sync.aligned.m8n8.x4.shared.b16 {%0,%1,%2,%3}, [%4];"
        : "=r"(r[0]), "=r"(r[1]), "=r"(r[2]), "=r"(r[3]) : "r"(addr));
}

__device__ __forceinline__ float tanh_fast(float y) {
    float r;
    asm("tanh.approx.f32 %0, %1;" : "=f"(r) : "f"(y));
    return r;
}

__global__ void __launch_bounds__(256, 2)
comm_v10(const float* __restrict__ x, const float* __restrict__ Wh,
         const float* __restrict__ Wc, float* __restrict__ out) {
    __shared__ __align__(16) char sm[SMEM_SZ];
    const uint32_t sb = smem_u32(sm);

    const int tid = threadIdx.x;
    const int w = tid >> 5, lane = tid & 31;
    const int g = w >> 1, c = w & 1;
    const int q = lane >> 2, j = lane & 3;

    // ---- W1' B-frags in regs (32), permuted logical columns ----
    uint32_t bW[4][4][2];
#pragma unroll
    for (int ks = 0; ks < 4; ks++) {
#pragma unroll
        for (int nb = 0; nb < 4; nb++) {
            int n = (c << 5) + ((nb >> 1) << 4) + ((q >> 1) << 2) +
                    ((nb & 1) << 1) + (q & 1);
            int i00 = n * 64 + ks * 16 + j * 2;
            int i10 = i00 + 8;
            float w00 = Wh[i00] - Wc[i00] * (1.0f / 7.0f);
            float w01 = Wh[i00 + 1] - Wc[i00 + 1] * (1.0f / 7.0f);
            float w10 = Wh[i10] - Wc[i10] * (1.0f / 7.0f);
            float w11 = Wh[i10 + 1] - Wc[i10 + 1] * (1.0f / 7.0f);
            bW[ks][nb][0] = pack_h2(w00, w01);
            bW[ks][nb][1] = pack_h2(w10, w11);
        }
    }
    // ---- W2 B-frags for T-GEMM (8 regs): warp covers e-cols w*8..w*8+7 ----
    uint32_t bT[4][2];
#pragma unroll
    for (int ks = 0; ks < 4; ks++) {
        int n = (w << 3) + q;
        int i00 = n * 64 + ks * 16 + j * 2;
        int i10 = i00 + 8;
        bT[ks][0] = pack_h2(Wc[i00] * (1.0f / 7.0f), Wc[i00 + 1] * (1.0f / 7.0f));
        bT[ks][1] = pack_h2(Wc[i10] * (1.0f / 7.0f), Wc[i10 + 1] * (1.0f / 7.0f));
    }

    // ---- invariants ----
    const int arow = lane & 15, ahi = lane >> 4;
    uint32_t abase[2];
    int ar7[2];
#pragma unroll
    for (int bt = 0; bt < 2; bt++) {
        int r = g * 16 + bt * 64 + arow;
        abase[bt] = (uint32_t)(r << 7);
        ar7[bt] = r & 7;
    }
    // staging: batch row b = 2w + (lane>>4), float4 col kc = lane&15
    const int bloc = 2 * w + (lane >> 4);
    const int kc = lane & 15;
    const uint32_t sts_sw = (uint32_t)((((kc >> 1))) << 4) + ((kc & 1) << 3);
    // s ldsm (16-row A frag from s tile)
    const uint32_t s_ld_base = (uint32_t)(arow << 7);
    const int s_r7 = arow & 7;

    const int grid = gridDim.x;
    int t = blockIdx.x, p = 0;

    // preload first tile
    float4 v[8];
    {
        const float4* xp =
            (const float4*)(x + (size_t)t * 8192 + bloc * 512 + kc * 4);
#pragma unroll
        for (int a = 0; a < 8; a++) v[a] = xp[a * 16];
    }

    for (;;) {
        // ---- convert + s ----
        {
            char* xb = sm + (p ? X1 : X0);
            char* sf = sm + (p ? S1 : S0);
            float sx = 0.f, sy = 0.f, sz = 0.f, sw = 0.f;
#pragma unroll
            for (int a = 0; a < 8; a++) {
                sx += v[a].x; sy += v[a].y; sz += v[a].z; sw += v[a].w;
                int r = bloc * 8 + a;
                uint32_t ro = (uint32_t)(r << 7) +
                              (sts_sw ^ (uint32_t)((r & 7) << 4));
                *(uint2*)(xb + ro) =
                    make_uint2(pack_h2(v[a].x, v[a].y), pack_h2(v[a].z, v[a].w));
            }
            uint32_t so = (uint32_t)(bloc << 7) +
                          (sts_sw ^ (uint32_t)((bloc & 7) << 4));
            *(uint2*)(sf + so) =
                make_uint2(pack_h2(sx, sy), pack_h2(sz, sw));
        }
        int tn = t + grid;
        bool more = (tn < NTILES);
        if (more) {  // prefetch next tile (in flight across syncs + GEMMs)
            const float4* xp =
                (const float4*)(x + (size_t)tn * 8192 + bloc * 512 + kc * 4);
#pragma unroll
            for (int a = 0; a < 8; a++) v[a] = xp[a * 16];
        }
        __syncthreads();

        // ---- T-GEMM: T[0..15, w*8..w*8+7] = s @ W2^T, 4 MMA ----
        {
            float accT[4] = {0.f, 0.f, 0.f, 0.f};
            const uint32_t sbase = sb + (p ? S1 : S0) + s_ld_base;
#pragma unroll
            for (int ks = 0; ks < 4; ks++) {
                uint32_t a4[4];
                ldsm4(a4, sbase + ((((2 * ks + ahi) ^ s_r7)) << 4));
                mma_fp16(accT, a4, bT[ks][0], bT[ks][1]);
            }
            float* Tb = (float*)(sm + (p ? T1 : T0));
            int tc = (w << 3) + (j << 1);
            *(float2*)(Tb + q * 64 + tc) = make_float2(accT[0], accT[1]);
            *(float2*)(Tb + (q + 8) * 64 + tc) = make_float2(accT[2], accT[3]);
        }
        __syncthreads();

        // ---- main GEMM: 8 ldsm4 + 32 MMA (W1' only) ----
        float acc[2][4][4] = {};
        const uint32_t xbb = sb + (p ? X1 : X0);
#pragma unroll
        for (int ks = 0; ks < 4; ks++) {
#pragma unroll
            for (int bt = 0; bt < 2; bt++) {
                uint32_t a[4];
                ldsm4(a, xbb + abase[bt] +
                             ((((2 * ks + ahi) ^ ar7[bt])) << 4));
#pragma unroll
                for (int nb = 0; nb < 4; nb++)
                    mma_fp16(acc[bt][nb], a, bW[ks][nb][0], bW[ks][nb][1]);
            }
        }

        // ---- epilogue: +T (broadcast LDS.128), tanh, STG.128 ----
        {
            const float* Tb = (const float*)(sm + (p ? T1 : T0));
#pragma unroll
            for (int bt = 0; bt < 2; bt++) {
#pragma unroll
                for (int h = 0; h < 2; h++) {
                    int bb = 2 * g + 8 * bt + h;
                    int R = t * 128 + g * 16 + bt * 64 + h * 8 + q;
                    const float* Trow = Tb + bb * 64 + (c << 5) + (j << 2);
                    float* op = out + (size_t)R * 64 + (c << 5) + (j << 2);
#pragma unroll
                    for (int m = 0; m < 2; m++) {
                        float4 tv = *(const float4*)(Trow + m * 16);
                        float4 o;
                        o.x = tanh_fast(acc[bt][2 * m][2 * h] + tv.x);
                        o.y = tanh_fast(acc[bt][2 * m][2 * h + 1] + tv.y);
                        o.z = tanh_fast(acc[bt][2 * m + 1][2 * h] + tv.z);
                        o.w = tanh_fast(acc[bt][2 * m + 1][2 * h + 1] + tv.w);
                        *(float4*)(op + m * 16) = o;
                    }
                }
            }
        }

        if (!more) break;
        t = tn;
        p ^= 1;
    }
}

extern "C" void kernel_launch(void* const* d_in, const int* in_sizes, int n_in,
                              void* d_out, int out_size) {
    const float* x  = (const float*)d_in[0];
    const float* Wh = (const float*)d_in[1];
    const float* Wc = (const float*)d_in[2];
    float* out = (float*)d_out;

    int dev = 0, sms = 148;
    cudaGetDevice(&dev);
    cudaDeviceGetAttribute(&sms, cudaDevAttrMultiProcessorCount, dev);

    comm_v10<<<2 * sms, 256>>>(x, Wh, Wc, out);
}